// round 12
// baseline (speedup 1.0000x reference)
#include <cuda_runtime.h>

// Problem constants
#define NB   4
#define NP   4096
#define CIN  128
#define FO   256
#define KNN  20
#define BNP  (NB*NP)          // 16384 points
#define NE   (BNP*KNN)        // 327680 edges

// ---------------------------------------------------------------------------
// Scratch (device globals — allocation-free kernel_launch)
// ---------------------------------------------------------------------------
__device__ float g_p   [(size_t)BNP*CIN];        // w1_w @ x        (per point)
__device__ float g_u   [(size_t)BNP*FO];         // (A1-B1)@x + b1  (per point)
__device__ float g_v   [(size_t)BNP*FO];         // B1@x            (per point)
__device__ float g_sq  [BNP];                    // ||x||^2 per point
__device__ float g_dist[(size_t)NB*NP*NP];       // pairwise distances
__device__ int   g_idx [NE];                     // knn indices (within batch)
__device__ float g_Q   [(size_t)NE*CIN];         // lrelu(conv1) per edge
__device__ float g_R   [(size_t)NE*FO];          // lrelu(x1)   per edge
__device__ float g_S   [(size_t)NE*FO];          // w2 output per edge
__device__ float g_H   [(size_t)NE*FO];          // x2 output per edge

typedef unsigned long long ull;

// ---------------------------------------------------------------------------
// f32x2 packed-FMA helpers (Blackwell FFMA2 path)
// ---------------------------------------------------------------------------
__device__ __forceinline__ ull bcast2(float x) {
    ull r; asm("mov.b64 %0, {%1, %1};" : "=l"(r) : "f"(x)); return r;
}
__device__ __forceinline__ void fma2(ull &d, ull a, ull b) {
    asm("fma.rn.f32x2 %0, %1, %2, %0;" : "+l"(d) : "l"(a), "l"(b));
}
__device__ __forceinline__ void unpack2(ull v, float &lo, float &hi) {
    asm("mov.b64 {%0, %1}, %2;" : "=f"(lo), "=f"(hi) : "l"(v));
}

// ---------------------------------------------------------------------------
// Generic SGEMM body:  C[m][n] = sum_k A[m][k] * Weff[n][k]  (+ epilogue)
//   Weff[n][k] = W[n*ldw + wOff + k]  (- W[n*ldw + wSub + k] if wSub >= 0)
// MODE 0: C += bias[n] (bias may be null)
// MODE 1: C = sq[m] + sq[n] - 2*acc   (distance epilogue, batched by blockIdx.z)
// BM = BN = 128, BK = 8, 256 threads, 8x8 micro-tile with f32x2 accumulators.
// Requires M,N multiples of 128; Kd multiple of 8.
// ---------------------------------------------------------------------------
template<int MODE>
__device__ __forceinline__ void sgemm_body(
    const float* __restrict__ A, int lda, size_t bsA,
    const float* __restrict__ W, int ldw, size_t bsW, int wOff, int wSub,
    const float* __restrict__ bias,
    float* __restrict__ C, int ldc, size_t bsC,
    int Kd, const float* __restrict__ sqv, int sqStride)
{
    __shared__ float As[8][128];
    __shared__ float Bs[8][128];

    const int tid     = threadIdx.x;
    const int tx      = tid & 15;
    const int ty      = tid >> 4;
    const int loadRow = tid >> 1;
    const int loadK   = (tid & 1) << 2;
    const int bz      = blockIdx.z;

    const float* Abase = A + (size_t)bz*bsA + (size_t)(blockIdx.y*128 + loadRow)*lda + loadK;
    const float* Wbase = W + (size_t)bz*bsW + (size_t)(blockIdx.x*128 + loadRow)*ldw + loadK;

    ull acc2[8][4];
    #pragma unroll
    for (int i = 0; i < 8; i++)
        #pragma unroll
        for (int j = 0; j < 4; j++) acc2[i][j] = 0ull;

    const int nK = Kd >> 3;

    float4 pa = *(const float4*)(Abase);
    float4 pw = *(const float4*)(Wbase + wOff);
    if (wSub >= 0) {
        float4 s = *(const float4*)(Wbase + wSub);
        pw.x -= s.x; pw.y -= s.y; pw.z -= s.z; pw.w -= s.w;
    }
    As[loadK+0][loadRow] = pa.x; As[loadK+1][loadRow] = pa.y;
    As[loadK+2][loadRow] = pa.z; As[loadK+3][loadRow] = pa.w;
    Bs[loadK+0][loadRow] = pw.x; Bs[loadK+1][loadRow] = pw.y;
    Bs[loadK+2][loadRow] = pw.z; Bs[loadK+3][loadRow] = pw.w;
    __syncthreads();

    for (int kt = 0; kt < nK; kt++) {
        if (kt + 1 < nK) {
            pa = *(const float4*)(Abase + (kt+1)*8);
            pw = *(const float4*)(Wbase + wOff + (kt+1)*8);
            if (wSub >= 0) {
                float4 s = *(const float4*)(Wbase + wSub + (kt+1)*8);
                pw.x -= s.x; pw.y -= s.y; pw.z -= s.z; pw.w -= s.w;
            }
        }
        #pragma unroll
        for (int k = 0; k < 8; k++) {
            float4 a0 = *(const float4*)&As[k][ty*4];
            float4 a1 = *(const float4*)&As[k][ty*4 + 64];
            ulonglong2 bb0 = *(const ulonglong2*)&Bs[k][tx*4];
            ulonglong2 bb1 = *(const ulonglong2*)&Bs[k][tx*4 + 64];
            float av[8] = {a0.x, a0.y, a0.z, a0.w, a1.x, a1.y, a1.z, a1.w};
            ull   bp[4] = {bb0.x, bb0.y, bb1.x, bb1.y};
            #pragma unroll
            for (int i = 0; i < 8; i++) {
                ull ai = bcast2(av[i]);
                #pragma unroll
                for (int jj = 0; jj < 4; jj++) fma2(acc2[i][jj], ai, bp[jj]);
            }
        }
        __syncthreads();
        if (kt + 1 < nK) {
            As[loadK+0][loadRow] = pa.x; As[loadK+1][loadRow] = pa.y;
            As[loadK+2][loadRow] = pa.z; As[loadK+3][loadRow] = pa.w;
            Bs[loadK+0][loadRow] = pw.x; Bs[loadK+1][loadRow] = pw.y;
            Bs[loadK+2][loadRow] = pw.z; Bs[loadK+3][loadRow] = pw.w;
        }
        __syncthreads();
    }

    const int gn0 = blockIdx.x*128 + tx*4;
    float badd[8];
    if (MODE == 0) {
        #pragma unroll
        for (int j = 0; j < 4; j++) {
            badd[j]   = bias ? bias[gn0 + j]      : 0.f;
            badd[4+j] = bias ? bias[gn0 + 64 + j] : 0.f;
        }
    } else {
        const float* sqc = sqv + (size_t)bz*sqStride;
        #pragma unroll
        for (int j = 0; j < 4; j++) { badd[j] = sqc[gn0 + j]; badd[4+j] = sqc[gn0 + 64 + j]; }
    }

    float* Cb = C + (size_t)bz*bsC;
    #pragma unroll
    for (int i = 0; i < 8; i++) {
        const int gm = blockIdx.y*128 + ty*4 + (i & 3) + ((i >> 2) << 6);
        float cc[8];
        #pragma unroll
        for (int jj = 0; jj < 4; jj++) { float lo, hi; unpack2(acc2[i][jj], lo, hi); cc[2*jj] = lo; cc[2*jj+1] = hi; }
        float4 o0, o1;
        if (MODE == 0) {
            o0 = make_float4(cc[0]+badd[0], cc[1]+badd[1], cc[2]+badd[2], cc[3]+badd[3]);
            o1 = make_float4(cc[4]+badd[4], cc[5]+badd[5], cc[6]+badd[6], cc[7]+badd[7]);
        } else {
            const float rs = sqv[(size_t)bz*sqStride + gm];
            o0 = make_float4(rs+badd[0]-2.f*cc[0], rs+badd[1]-2.f*cc[1],
                             rs+badd[2]-2.f*cc[2], rs+badd[3]-2.f*cc[3]);
            o1 = make_float4(rs+badd[4]-2.f*cc[4], rs+badd[5]-2.f*cc[5],
                             rs+badd[6]-2.f*cc[6], rs+badd[7]-2.f*cc[7]);
        }
        *(float4*)&Cb[(size_t)gm*ldc + gn0]      = o0;
        *(float4*)&Cb[(size_t)gm*ldc + gn0 + 64] = o1;
    }
}

// ---------------------------------------------------------------------------
// GEMM wrappers (bind device-global scratch — keeps kernel_launch launch-only)
// ---------------------------------------------------------------------------
__global__ void __launch_bounds__(256, 2) gemm_p(const float* x, const float* w1w) {
    sgemm_body<0>(x, CIN, 0, w1w, CIN, 0, 0, -1, nullptr, g_p, CIN, 0, CIN, nullptr, 0);
}
__global__ void __launch_bounds__(256, 2) gemm_v(const float* x, const float* x1w) {
    sgemm_body<0>(x, CIN, 0, x1w, 256, 0, 128, -1, nullptr, g_v, FO, 0, CIN, nullptr, 0);
}
__global__ void __launch_bounds__(256, 2) gemm_u(const float* x, const float* x1w, const float* x1b) {
    sgemm_body<0>(x, CIN, 0, x1w, 256, 0, 0, 128, x1b, g_u, FO, 0, CIN, nullptr, 0);
}
__global__ void __launch_bounds__(256, 2) gemm_dist(const float* x) {
    sgemm_body<1>(x, CIN, (size_t)NP*CIN, x, CIN, (size_t)NP*CIN, 0, -1, nullptr,
                  g_dist, NP, (size_t)NP*NP, CIN, g_sq, NP);
}
__global__ void __launch_bounds__(256, 2) gemm_S(const float* w2w, const float* w2b) {
    sgemm_body<0>(g_Q, CIN, 0, w2w, CIN, 0, 0, -1, w2b, g_S, FO, 0, CIN, nullptr, 0);
}
__global__ void __launch_bounds__(256, 2) gemm_H(const float* x2w, const float* x2b) {
    sgemm_body<0>(g_R, FO, 0, x2w, FO, 0, 0, -1, x2b, g_H, FO, 0, FO, nullptr, 0);
}

// ---------------------------------------------------------------------------
// ||x||^2 per point: one warp per row of 128 floats
// ---------------------------------------------------------------------------
__global__ void __launch_bounds__(256) sq_kernel(const float* __restrict__ x) {
    const int row  = blockIdx.x*8 + (threadIdx.x >> 5);
    const int lane = threadIdx.x & 31;
    float4 v = ((const float4*)(x + (size_t)row*CIN))[lane];
    float s = v.x*v.x + v.y*v.y + v.z*v.z + v.w*v.w;
    #pragma unroll
    for (int off = 16; off > 0; off >>= 1) s += __shfl_xor_sync(0xffffffffu, s, off);
    if (lane == 0) g_sq[row] = s;
}

// ---------------------------------------------------------------------------
// Top-20 nearest (excluding self): one warp per query row.
// Per-lane unsorted top-20 of packed (orderable_dist<<32 | idx) keys in regs,
// then 20 rounds of warp-argmin merge. Keys are unique (idx in low bits).
// ---------------------------------------------------------------------------
__global__ void __launch_bounds__(256) topk_kernel() {
    const int gw   = blockIdx.x*8 + (threadIdx.x >> 5);
    const int lane = threadIdx.x & 31;
    const int n    = gw & (NP - 1);
    const float* row = g_dist + (size_t)gw * NP;

    ull best[KNN];
    #pragma unroll
    for (int j = 0; j < KNN; j++) best[j] = ~0ull;
    ull curmax = ~0ull; int maxslot = 0;

    for (int m = lane; m < NP; m += 32) {
        if (m == n) continue;
        float d = row[m];
        unsigned ub = __float_as_uint(d);
        ub = (ub & 0x80000000u) ? ~ub : (ub | 0x80000000u);
        ull key = ((ull)ub << 32) | (unsigned)m;
        if (key < curmax) {
            #pragma unroll
            for (int j = 0; j < KNN; j++) if (j == maxslot) best[j] = key;
            curmax = best[0]; maxslot = 0;
            #pragma unroll
            for (int j = 1; j < KNN; j++) if (best[j] > curmax) { curmax = best[j]; maxslot = j; }
        }
    }

    #pragma unroll 1
    for (int r = 0; r < KNN; r++) {
        ull lmin = best[0]; int ls = 0;
        #pragma unroll
        for (int j = 1; j < KNN; j++) if (best[j] < lmin) { lmin = best[j]; ls = j; }
        ull wmin = lmin;
        #pragma unroll
        for (int off = 16; off > 0; off >>= 1) {
            ull o = __shfl_xor_sync(0xffffffffu, wmin, off);
            if (o < wmin) wmin = o;
        }
        if (lmin == wmin) {
            #pragma unroll
            for (int j = 0; j < KNN; j++) if (j == ls) best[j] = ~0ull;
        }
        if (lane == 0) g_idx[gw*KNN + r] = (int)(wmin & 0xffffffffull);
    }
}

// ---------------------------------------------------------------------------
// Gather + lrelu:  Q[e] = lrelu(p[nbr]-p[n]+w1_b)   R[e] = lrelu(u[n]+v[nbr])
// One block per edge, 128 threads (channel-parallel, coalesced).
// ---------------------------------------------------------------------------
__global__ void __launch_bounds__(128) build_kernel(const float* __restrict__ w1b) {
    const int e   = blockIdx.x;
    const int c   = threadIdx.x;
    const int bn  = e / KNN;
    const int b   = bn >> 12;
    const int nbr = (b << 12) + g_idx[e];

    float q = g_p[(size_t)nbr*CIN + c] - g_p[(size_t)bn*CIN + c] + w1b[c];
    g_Q[(size_t)e*CIN + c] = fmaxf(q, 0.2f*q);

    float r0 = g_u[(size_t)bn*FO + c] + g_v[(size_t)nbr*FO + c];
    g_R[(size_t)e*FO + c] = fmaxf(r0, 0.2f*r0);
    float r1 = g_u[(size_t)bn*FO + 128 + c] + g_v[(size_t)nbr*FO + 128 + c];
    g_R[(size_t)e*FO + 128 + c] = fmaxf(r1, 0.2f*r1);
}

// ---------------------------------------------------------------------------
// Softmax over K + weighted sum:  out[bn,c] = sum_k H*softmax_k(S)
// One thread per (point, channel); k-strided reads are coalesced across c.
// ---------------------------------------------------------------------------
__global__ void __launch_bounds__(256) smax_kernel(float* __restrict__ out) {
    const int bn = blockIdx.x;
    const int c  = threadIdx.x;
    const size_t base = (size_t)bn*KNN*FO + c;

    float sv[KNN];
    float mx = -3.4e38f;
    #pragma unroll
    for (int k = 0; k < KNN; k++) { sv[k] = g_S[base + (size_t)k*FO]; mx = fmaxf(mx, sv[k]); }
    float sum = 0.f, acc = 0.f;
    #pragma unroll
    for (int k = 0; k < KNN; k++) {
        float e = expf(sv[k] - mx);
        sum += e;
        acc += e * g_H[base + (size_t)k*FO];
    }
    out[(size_t)bn*FO + c] = acc / sum;
}

// ---------------------------------------------------------------------------
// Launch
// ---------------------------------------------------------------------------
extern "C" void kernel_launch(void* const* d_in, const int* in_sizes, int n_in,
                              void* d_out, int out_size) {
    const float* x   = (const float*)d_in[0];
    const float* w1w = (const float*)d_in[1];
    const float* w1b = (const float*)d_in[2];
    const float* w2w = (const float*)d_in[3];
    const float* w2b = (const float*)d_in[4];
    const float* x1w = (const float*)d_in[5];
    const float* x1b = (const float*)d_in[6];
    const float* x2w = (const float*)d_in[7];
    const float* x2b = (const float*)d_in[8];
    float* out = (float*)d_out;

    // Per-point squared norms + per-point linear features
    sq_kernel<<<BNP/8, 256>>>(x);
    gemm_p<<<dim3(1, BNP/128, 1), 256>>>(x, w1w);
    gemm_v<<<dim3(2, BNP/128, 1), 256>>>(x, x1w);
    gemm_u<<<dim3(2, BNP/128, 1), 256>>>(x, x1w, x1b);

    // Pairwise distances (per batch) + top-20 neighbors
    gemm_dist<<<dim3(NP/128, NP/128, NB), 256>>>(x);
    topk_kernel<<<BNP/8, 256>>>();

    // Per-edge feature assembly (gather + bias + lrelu)
    build_kernel<<<NE, 128>>>(w1b);

    // Per-edge GEMMs
    gemm_S<<<dim3(2, NE/128, 1), 256>>>(w2w, w2b);
    gemm_H<<<dim3(2, NE/128, 1), 256>>>(x2w, x2b);

    // Softmax over K + weighted reduction -> output (B,N,256)
    smax_kernel<<<BNP, 256>>>(out);
}

// round 13
// speedup vs baseline: 1.5768x; 1.5768x over previous
#include <cuda_runtime.h>

// Problem constants
#define NB   4
#define NP   4096
#define CIN  128
#define FO   256
#define KNN  20
#define BNP  (NB*NP)          // 16384 points
#define NE   (BNP*KNN)        // 327680 edges

// ---------------------------------------------------------------------------
// Scratch (device globals — allocation-free kernel_launch)
// ---------------------------------------------------------------------------
__device__ float g_p   [(size_t)BNP*CIN];        // w1_w @ x        (per point)
__device__ float g_u   [(size_t)BNP*FO];         // (A1-B1)@x + b1  (per point)
__device__ float g_v   [(size_t)BNP*FO];         // B1@x            (per point)
__device__ float g_sq  [BNP];                    // ||x||^2 per point
__device__ float g_dist[(size_t)NB*NP*NP];       // pairwise distances
__device__ int   g_idx [NE];                     // knn indices (within batch)
__device__ float g_Q   [(size_t)NE*CIN];         // lrelu(conv1) per edge
__device__ float g_R   [(size_t)NE*FO];          // lrelu(x1)   per edge
__device__ float g_S   [(size_t)NE*FO];          // w2 output per edge
__device__ float g_H   [(size_t)NE*FO];          // x2 output per edge

typedef unsigned long long ull;

// ---------------------------------------------------------------------------
// f32x2 packed-FMA helpers (Blackwell FFMA2 path)
// ---------------------------------------------------------------------------
__device__ __forceinline__ ull bcast2(float x) {
    ull r; asm("mov.b64 %0, {%1, %1};" : "=l"(r) : "f"(x)); return r;
}
__device__ __forceinline__ void fma2(ull &d, ull a, ull b) {
    asm("fma.rn.f32x2 %0, %1, %2, %0;" : "+l"(d) : "l"(a), "l"(b));
}
__device__ __forceinline__ void unpack2(ull v, float &lo, float &hi) {
    asm("mov.b64 {%0, %1}, %2;" : "=f"(lo), "=f"(hi) : "l"(v));
}

// ---------------------------------------------------------------------------
// Generic SGEMM body:  C[m][n] = sum_k A[m][k] * Weff[n][k]  (+ epilogue)
//   Weff[n][k] = W[n*ldw + wOff + k]  (- W[n*ldw + wSub + k] if wSub >= 0)
// MODE 0: C += bias[n] (bias may be null)
// MODE 1: C = sq[m] + sq[n] - 2*acc   (distance epilogue, batched by blockIdx.z)
// BM = BN = 128, BK = 8, 256 threads, 8x8 micro-tile with f32x2 accumulators.
// Requires M,N multiples of 128; Kd multiple of 8.
// ---------------------------------------------------------------------------
template<int MODE>
__device__ __forceinline__ void sgemm_body(
    const float* __restrict__ A, int lda, size_t bsA,
    const float* __restrict__ W, int ldw, size_t bsW, int wOff, int wSub,
    const float* __restrict__ bias,
    float* __restrict__ C, int ldc, size_t bsC,
    int Kd, const float* __restrict__ sqv, int sqStride)
{
    __shared__ float As[8][128];
    __shared__ float Bs[8][128];

    const int tid     = threadIdx.x;
    const int tx      = tid & 15;
    const int ty      = tid >> 4;
    const int loadRow = tid >> 1;
    const int loadK   = (tid & 1) << 2;
    const int bz      = blockIdx.z;

    const float* Abase = A + (size_t)bz*bsA + (size_t)(blockIdx.y*128 + loadRow)*lda + loadK;
    const float* Wbase = W + (size_t)bz*bsW + (size_t)(blockIdx.x*128 + loadRow)*ldw + loadK;

    ull acc2[8][4];
    #pragma unroll
    for (int i = 0; i < 8; i++)
        #pragma unroll
        for (int j = 0; j < 4; j++) acc2[i][j] = 0ull;

    const int nK = Kd >> 3;

    float4 pa = *(const float4*)(Abase);
    float4 pw = *(const float4*)(Wbase + wOff);
    if (wSub >= 0) {
        float4 s = *(const float4*)(Wbase + wSub);
        pw.x -= s.x; pw.y -= s.y; pw.z -= s.z; pw.w -= s.w;
    }
    As[loadK+0][loadRow] = pa.x; As[loadK+1][loadRow] = pa.y;
    As[loadK+2][loadRow] = pa.z; As[loadK+3][loadRow] = pa.w;
    Bs[loadK+0][loadRow] = pw.x; Bs[loadK+1][loadRow] = pw.y;
    Bs[loadK+2][loadRow] = pw.z; Bs[loadK+3][loadRow] = pw.w;
    __syncthreads();

    for (int kt = 0; kt < nK; kt++) {
        if (kt + 1 < nK) {
            pa = *(const float4*)(Abase + (kt+1)*8);
            pw = *(const float4*)(Wbase + wOff + (kt+1)*8);
            if (wSub >= 0) {
                float4 s = *(const float4*)(Wbase + wSub + (kt+1)*8);
                pw.x -= s.x; pw.y -= s.y; pw.z -= s.z; pw.w -= s.w;
            }
        }
        #pragma unroll
        for (int k = 0; k < 8; k++) {
            float4 a0 = *(const float4*)&As[k][ty*4];
            float4 a1 = *(const float4*)&As[k][ty*4 + 64];
            ulonglong2 bb0 = *(const ulonglong2*)&Bs[k][tx*4];
            ulonglong2 bb1 = *(const ulonglong2*)&Bs[k][tx*4 + 64];
            float av[8] = {a0.x, a0.y, a0.z, a0.w, a1.x, a1.y, a1.z, a1.w};
            ull   bp[4] = {bb0.x, bb0.y, bb1.x, bb1.y};
            #pragma unroll
            for (int i = 0; i < 8; i++) {
                ull ai = bcast2(av[i]);
                #pragma unroll
                for (int jj = 0; jj < 4; jj++) fma2(acc2[i][jj], ai, bp[jj]);
            }
        }
        __syncthreads();
        if (kt + 1 < nK) {
            As[loadK+0][loadRow] = pa.x; As[loadK+1][loadRow] = pa.y;
            As[loadK+2][loadRow] = pa.z; As[loadK+3][loadRow] = pa.w;
            Bs[loadK+0][loadRow] = pw.x; Bs[loadK+1][loadRow] = pw.y;
            Bs[loadK+2][loadRow] = pw.z; Bs[loadK+3][loadRow] = pw.w;
        }
        __syncthreads();
    }

    const int gn0 = blockIdx.x*128 + tx*4;
    float badd[8];
    if (MODE == 0) {
        #pragma unroll
        for (int j = 0; j < 4; j++) {
            badd[j]   = bias ? bias[gn0 + j]      : 0.f;
            badd[4+j] = bias ? bias[gn0 + 64 + j] : 0.f;
        }
    } else {
        const float* sqc = sqv + (size_t)bz*sqStride;
        #pragma unroll
        for (int j = 0; j < 4; j++) { badd[j] = sqc[gn0 + j]; badd[4+j] = sqc[gn0 + 64 + j]; }
    }

    float* Cb = C + (size_t)bz*bsC;
    #pragma unroll
    for (int i = 0; i < 8; i++) {
        const int gm = blockIdx.y*128 + ty*4 + (i & 3) + ((i >> 2) << 6);
        float cc[8];
        #pragma unroll
        for (int jj = 0; jj < 4; jj++) { float lo, hi; unpack2(acc2[i][jj], lo, hi); cc[2*jj] = lo; cc[2*jj+1] = hi; }
        float4 o0, o1;
        if (MODE == 0) {
            o0 = make_float4(cc[0]+badd[0], cc[1]+badd[1], cc[2]+badd[2], cc[3]+badd[3]);
            o1 = make_float4(cc[4]+badd[4], cc[5]+badd[5], cc[6]+badd[6], cc[7]+badd[7]);
        } else {
            const float rs = sqv[(size_t)bz*sqStride + gm];
            o0 = make_float4(rs+badd[0]-2.f*cc[0], rs+badd[1]-2.f*cc[1],
                             rs+badd[2]-2.f*cc[2], rs+badd[3]-2.f*cc[3]);
            o1 = make_float4(rs+badd[4]-2.f*cc[4], rs+badd[5]-2.f*cc[5],
                             rs+badd[6]-2.f*cc[6], rs+badd[7]-2.f*cc[7]);
        }
        *(float4*)&Cb[(size_t)gm*ldc + gn0]      = o0;
        *(float4*)&Cb[(size_t)gm*ldc + gn0 + 64] = o1;
    }
}

// ---------------------------------------------------------------------------
// GEMM wrappers (bind device-global scratch — keeps kernel_launch launch-only)
// ---------------------------------------------------------------------------
__global__ void __launch_bounds__(256, 2) gemm_p(const float* x, const float* w1w) {
    sgemm_body<0>(x, CIN, 0, w1w, CIN, 0, 0, -1, nullptr, g_p, CIN, 0, CIN, nullptr, 0);
}
__global__ void __launch_bounds__(256, 2) gemm_v(const float* x, const float* x1w) {
    sgemm_body<0>(x, CIN, 0, x1w, 256, 0, 128, -1, nullptr, g_v, FO, 0, CIN, nullptr, 0);
}
__global__ void __launch_bounds__(256, 2) gemm_u(const float* x, const float* x1w, const float* x1b) {
    sgemm_body<0>(x, CIN, 0, x1w, 256, 0, 0, 128, x1b, g_u, FO, 0, CIN, nullptr, 0);
}
__global__ void __launch_bounds__(256, 2) gemm_dist(const float* x) {
    sgemm_body<1>(x, CIN, (size_t)NP*CIN, x, CIN, (size_t)NP*CIN, 0, -1, nullptr,
                  g_dist, NP, (size_t)NP*NP, CIN, g_sq, NP);
}
__global__ void __launch_bounds__(256, 2) gemm_S(const float* w2w, const float* w2b) {
    sgemm_body<0>(g_Q, CIN, 0, w2w, CIN, 0, 0, -1, w2b, g_S, FO, 0, CIN, nullptr, 0);
}
__global__ void __launch_bounds__(256, 2) gemm_H(const float* x2w, const float* x2b) {
    sgemm_body<0>(g_R, FO, 0, x2w, FO, 0, 0, -1, x2b, g_H, FO, 0, FO, nullptr, 0);
}

// ---------------------------------------------------------------------------
// ||x||^2 per point: one warp per row of 128 floats
// ---------------------------------------------------------------------------
__global__ void __launch_bounds__(256) sq_kernel(const float* __restrict__ x) {
    const int row  = blockIdx.x*8 + (threadIdx.x >> 5);
    const int lane = threadIdx.x & 31;
    float4 v = ((const float4*)(x + (size_t)row*CIN))[lane];
    float s = v.x*v.x + v.y*v.y + v.z*v.z + v.w*v.w;
    #pragma unroll
    for (int off = 16; off > 0; off >>= 1) s += __shfl_xor_sync(0xffffffffu, s, off);
    if (lane == 0) g_sq[row] = s;
}

// ---------------------------------------------------------------------------
// Top-20 nearest (excluding self): one warp per query row.
// Per-lane unsorted top-20 of packed (orderable_dist<<32 | idx) keys in regs,
// then 20 rounds of warp-argmin merge. Keys are unique (idx in low bits).
// ---------------------------------------------------------------------------
__global__ void __launch_bounds__(256) topk_kernel() {
    const int gw   = blockIdx.x*8 + (threadIdx.x >> 5);
    const int lane = threadIdx.x & 31;
    const int n    = gw & (NP - 1);
    const float* row = g_dist + (size_t)gw * NP;

    ull best[KNN];
    #pragma unroll
    for (int j = 0; j < KNN; j++) best[j] = ~0ull;
    ull curmax = ~0ull; int maxslot = 0;

    for (int m = lane; m < NP; m += 32) {
        if (m == n) continue;
        float d = row[m];
        unsigned ub = __float_as_uint(d);
        ub = (ub & 0x80000000u) ? ~ub : (ub | 0x80000000u);
        ull key = ((ull)ub << 32) | (unsigned)m;
        if (key < curmax) {
            #pragma unroll
            for (int j = 0; j < KNN; j++) if (j == maxslot) best[j] = key;
            curmax = best[0]; maxslot = 0;
            #pragma unroll
            for (int j = 1; j < KNN; j++) if (best[j] > curmax) { curmax = best[j]; maxslot = j; }
        }
    }

    #pragma unroll 1
    for (int r = 0; r < KNN; r++) {
        ull lmin = best[0]; int ls = 0;
        #pragma unroll
        for (int j = 1; j < KNN; j++) if (best[j] < lmin) { lmin = best[j]; ls = j; }
        ull wmin = lmin;
        #pragma unroll
        for (int off = 16; off > 0; off >>= 1) {
            ull o = __shfl_xor_sync(0xffffffffu, wmin, off);
            if (o < wmin) wmin = o;
        }
        if (lmin == wmin) {
            #pragma unroll
            for (int j = 0; j < KNN; j++) if (j == ls) best[j] = ~0ull;
        }
        if (lane == 0) g_idx[gw*KNN + r] = (int)(wmin & 0xffffffffull);
    }
}

// ---------------------------------------------------------------------------
// Gather + lrelu:  Q[e] = lrelu(p[nbr]-p[n]+w1_b)   R[e] = lrelu(u[n]+v[nbr])
// One block per edge, 128 threads (channel-parallel, coalesced).
// ---------------------------------------------------------------------------
__global__ void __launch_bounds__(128) build_kernel(const float* __restrict__ w1b) {
    const int e   = blockIdx.x;
    const int c   = threadIdx.x;
    const int bn  = e / KNN;
    const int b   = bn >> 12;
    const int nbr = (b << 12) + g_idx[e];

    float q = g_p[(size_t)nbr*CIN + c] - g_p[(size_t)bn*CIN + c] + w1b[c];
    g_Q[(size_t)e*CIN + c] = fmaxf(q, 0.2f*q);

    float r0 = g_u[(size_t)bn*FO + c] + g_v[(size_t)nbr*FO + c];
    g_R[(size_t)e*FO + c] = fmaxf(r0, 0.2f*r0);
    float r1 = g_u[(size_t)bn*FO + 128 + c] + g_v[(size_t)nbr*FO + 128 + c];
    g_R[(size_t)e*FO + 128 + c] = fmaxf(r1, 0.2f*r1);
}

// ---------------------------------------------------------------------------
// Softmax over K + weighted sum:  out[bn,c] = sum_k H*softmax_k(S)
// One thread per (point, channel); k-strided reads are coalesced across c.
// ---------------------------------------------------------------------------
__global__ void __launch_bounds__(256) smax_kernel(float* __restrict__ out) {
    const int bn = blockIdx.x;
    const int c  = threadIdx.x;
    const size_t base = (size_t)bn*KNN*FO + c;

    float sv[KNN];
    float mx = -3.4e38f;
    #pragma unroll
    for (int k = 0; k < KNN; k++) { sv[k] = g_S[base + (size_t)k*FO]; mx = fmaxf(mx, sv[k]); }
    float sum = 0.f, acc = 0.f;
    #pragma unroll
    for (int k = 0; k < KNN; k++) {
        float e = expf(sv[k] - mx);
        sum += e;
        acc += e * g_H[base + (size_t)k*FO];
    }
    out[(size_t)bn*FO + c] = acc / sum;
}

// ---------------------------------------------------------------------------
// Launch
// ---------------------------------------------------------------------------
extern "C" void kernel_launch(void* const* d_in, const int* in_sizes, int n_in,
                              void* d_out, int out_size) {
    const float* x   = (const float*)d_in[0];
    const float* w1w = (const float*)d_in[1];
    const float* w1b = (const float*)d_in[2];
    const float* w2w = (const float*)d_in[3];
    const float* w2b = (const float*)d_in[4];
    const float* x1w = (const float*)d_in[5];
    const float* x1b = (const float*)d_in[6];
    const float* x2w = (const float*)d_in[7];
    const float* x2b = (const float*)d_in[8];
    float* out = (float*)d_out;

    // Per-point squared norms + per-point linear features
    sq_kernel<<<BNP/8, 256>>>(x);
    gemm_p<<<dim3(1, BNP/128, 1), 256>>>(x, w1w);
    gemm_v<<<dim3(2, BNP/128, 1), 256>>>(x, x1w);
    gemm_u<<<dim3(2, BNP/128, 1), 256>>>(x, x1w, x1b);

    // Pairwise distances (per batch) + top-20 neighbors
    gemm_dist<<<dim3(NP/128, NP/128, NB), 256>>>(x);
    topk_kernel<<<BNP/8, 256>>>();

    // Per-edge feature assembly (gather + bias + lrelu)
    build_kernel<<<NE, 128>>>(w1b);

    // Per-edge GEMMs
    gemm_S<<<dim3(2, NE/128, 1), 256>>>(w2w, w2b);
    gemm_H<<<dim3(2, NE/128, 1), 256>>>(x2w, x2b);

    // Softmax over K + weighted reduction -> output (B,N,256)
    smax_kernel<<<BNP, 256>>>(out);
}

// round 14
// speedup vs baseline: 1.6050x; 1.0179x over previous
#include <cuda_runtime.h>

// Problem constants
#define NB   4
#define NP   4096
#define CIN  128
#define FO   256
#define KNN  20
#define BNP  (NB*NP)          // 16384 points
#define NE   (BNP*KNN)        // 327680 edges

// ---------------------------------------------------------------------------
// Scratch (device globals — allocation-free kernel_launch)
// ---------------------------------------------------------------------------
__device__ float g_p   [(size_t)BNP*CIN];        // w1_w @ x        (per point)
__device__ float g_u   [(size_t)BNP*FO];         // (A1-B1)@x + b1  (per point)
__device__ float g_v   [(size_t)BNP*FO];         // B1@x            (per point)
__device__ float g_sq  [BNP];                    // ||x||^2 per point
__device__ float g_dist[(size_t)NB*NP*NP];       // pairwise distances
__device__ int   g_idx [NE];                     // knn indices (within batch)
__device__ float g_S   [(size_t)NE*FO];          // w2 output per edge
__device__ float g_H   [(size_t)NE*FO];          // x2 output per edge

typedef unsigned long long ull;

// ---------------------------------------------------------------------------
// f32x2 packed-FMA helpers (Blackwell FFMA2 path)
// ---------------------------------------------------------------------------
__device__ __forceinline__ ull bcast2(float x) {
    ull r; asm("mov.b64 %0, {%1, %1};" : "=l"(r) : "f"(x)); return r;
}
__device__ __forceinline__ void fma2(ull &d, ull a, ull b) {
    asm("fma.rn.f32x2 %0, %1, %2, %0;" : "+l"(d) : "l"(a), "l"(b));
}
__device__ __forceinline__ void unpack2(ull v, float &lo, float &hi) {
    asm("mov.b64 {%0, %1}, %2;" : "=f"(lo), "=f"(hi) : "l"(v));
}
__device__ __forceinline__ float lrelu_f(float x) { return fmaxf(x, 0.2f*x); }

// ---------------------------------------------------------------------------
// SGEMM v2:  C[m][n] = sum_k Aeff[m][k] * Weff[n][k]  (+ epilogue)
//
//  AMODE 0: Aeff = A[m*lda + k]                       (plain)
//  AMODE 2: Aeff = lrelu(p[nbr(m)][k] - p[pt(m)][k] + w1b[k])   (fused Q)
//  AMODE 3: Aeff = lrelu(u[pt(m)][k] + v[nbr(m)][k])            (fused R)
//  Weff[n][k] = W[n*ldw + wOff + k] (- W[n*ldw + wSub + k] if wSub>=0)
//
//  EPI 0: C = acc + bias[n] (bias may be null)
//  EPI 1: C = sq[m] + sq[n] - 2*acc  (distance, batched by blockIdx.z)
//
// BM=BN=128, BK=8, 256 threads, 8x8 micro-tile, f32x2 accumulators.
// Double-buffered smem (1 sync/tile) + register-double-buffered fragments.
// ---------------------------------------------------------------------------
template<int AMODE, int EPI>
__device__ __forceinline__ void sgemm_body(
    const float* __restrict__ A, int lda, size_t bsA,
    const float* __restrict__ W, int ldw, size_t bsW, int wOff, int wSub,
    const float* __restrict__ bias,
    float* __restrict__ C, int ldc, size_t bsC,
    int Kd, const float* __restrict__ sqv, int sqStride,
    const float* __restrict__ P0, const float* __restrict__ P1,
    const float* __restrict__ w1b)
{
    __shared__ __align__(16) float As[2][8][128];
    __shared__ __align__(16) float Bs[2][8][128];

    const int tid  = threadIdx.x;
    const int lrow = tid & 127;          // row within tile (load mapping)
    const int lk   = (tid >> 7) * 4;     // k-quad within BK=8
    const int tx   = tid & 15;
    const int ty   = tid >> 4;
    const int bz   = blockIdx.z;

    const int am = blockIdx.y*128 + lrow;     // global A row (point or edge)

    // Fused-loader precompute (edge -> (point, neighbor) indices)
    int ebn = 0, enbr = 0;
    if (AMODE >= 2) {
        ebn  = am / KNN;
        enbr = ((ebn >> 12) << 12) + g_idx[am];
    }

    const float* Abase = (AMODE == 0)
        ? (A + (size_t)bz*bsA + (size_t)am*lda + lk) : nullptr;
    const float* Wbase = W + (size_t)bz*bsW
        + (size_t)(blockIdx.x*128 + lrow)*ldw + lk;

    ull acc2[8][4];
    #pragma unroll
    for (int i = 0; i < 8; i++)
        #pragma unroll
        for (int j = 0; j < 4; j++) acc2[i][j] = 0ull;

    const int nK = Kd >> 3;

    // ---- operand loaders (4 floats per thread per tile per operand) ----
    #define LOAD_A(kbase, out) do {                                          \
        if (AMODE == 0) {                                                     \
            float4 t = *(const float4*)(Abase + (kbase));                     \
            out[0]=t.x; out[1]=t.y; out[2]=t.z; out[3]=t.w;                   \
        } else if (AMODE == 2) {                                              \
            float4 a = *(const float4*)(P0 + (size_t)enbr*CIN + (kbase) + lk);\
            float4 b = *(const float4*)(P0 + (size_t)ebn *CIN + (kbase) + lk);\
            float4 w = *(const float4*)(w1b + (kbase) + lk);                  \
            out[0]=lrelu_f(a.x-b.x+w.x); out[1]=lrelu_f(a.y-b.y+w.y);         \
            out[2]=lrelu_f(a.z-b.z+w.z); out[3]=lrelu_f(a.w-b.w+w.w);         \
        } else {                                                              \
            float4 a = *(const float4*)(P0 + (size_t)ebn *FO + (kbase) + lk); \
            float4 b = *(const float4*)(P1 + (size_t)enbr*FO + (kbase) + lk); \
            out[0]=lrelu_f(a.x+b.x); out[1]=lrelu_f(a.y+b.y);                 \
            out[2]=lrelu_f(a.z+b.z); out[3]=lrelu_f(a.w+b.w);                 \
        }                                                                     \
    } while (0)

    #define LOAD_W(kbase, out) do {                                          \
        float4 t = *(const float4*)(Wbase + wOff + (kbase));                  \
        if (wSub >= 0) {                                                      \
            float4 s = *(const float4*)(Wbase + wSub + (kbase));              \
            t.x-=s.x; t.y-=s.y; t.z-=s.z; t.w-=s.w;                           \
        }                                                                     \
        out[0]=t.x; out[1]=t.y; out[2]=t.z; out[3]=t.w;                       \
    } while (0)

    #define STORE_TILE(buf, ra, rw) do {                                     \
        _Pragma("unroll")                                                     \
        for (int j = 0; j < 4; j++) {                                         \
            As[buf][lk+j][lrow] = ra[j];                                      \
            Bs[buf][lk+j][lrow] = rw[j];                                      \
        }                                                                     \
    } while (0)

    // prologue: tile 0 -> smem[0]
    {
        float ra[4], rw[4];
        LOAD_A(0, ra); LOAD_W(0, rw);
        STORE_TILE(0, ra, rw);
    }
    __syncthreads();

    int buf = 0;
    for (int kt = 0; kt < nK; kt++) {
        float na[4], nw[4];
        const bool more = (kt + 1 < nK);
        if (more) { LOAD_A((kt+1)*8, na); LOAD_W((kt+1)*8, nw); }

        // 8 k-steps, register double-buffered fragments
        float af[2][8];
        ull   bf[2][4];
        {
            float4 a0 = *(const float4*)&As[buf][0][ty*4];
            float4 a1 = *(const float4*)&As[buf][0][ty*4 + 64];
            af[0][0]=a0.x; af[0][1]=a0.y; af[0][2]=a0.z; af[0][3]=a0.w;
            af[0][4]=a1.x; af[0][5]=a1.y; af[0][6]=a1.z; af[0][7]=a1.w;
            ulonglong2 b0 = *(const ulonglong2*)&Bs[buf][0][tx*4];
            ulonglong2 b1 = *(const ulonglong2*)&Bs[buf][0][tx*4 + 64];
            bf[0][0]=b0.x; bf[0][1]=b0.y; bf[0][2]=b1.x; bf[0][3]=b1.y;
        }
        #pragma unroll
        for (int k = 0; k < 8; k++) {
            const int cur = k & 1, nxt = cur ^ 1;
            if (k < 7) {
                float4 a0 = *(const float4*)&As[buf][k+1][ty*4];
                float4 a1 = *(const float4*)&As[buf][k+1][ty*4 + 64];
                af[nxt][0]=a0.x; af[nxt][1]=a0.y; af[nxt][2]=a0.z; af[nxt][3]=a0.w;
                af[nxt][4]=a1.x; af[nxt][5]=a1.y; af[nxt][6]=a1.z; af[nxt][7]=a1.w;
                ulonglong2 b0 = *(const ulonglong2*)&Bs[buf][k+1][tx*4];
                ulonglong2 b1 = *(const ulonglong2*)&Bs[buf][k+1][tx*4 + 64];
                bf[nxt][0]=b0.x; bf[nxt][1]=b0.y; bf[nxt][2]=b1.x; bf[nxt][3]=b1.y;
            }
            #pragma unroll
            for (int i = 0; i < 8; i++) {
                ull ai = bcast2(af[cur][i]);
                #pragma unroll
                for (int jj = 0; jj < 4; jj++) fma2(acc2[i][jj], ai, bf[cur][jj]);
            }
        }

        if (more) STORE_TILE(buf ^ 1, na, nw);
        __syncthreads();
        buf ^= 1;
    }

    #undef LOAD_A
    #undef LOAD_W
    #undef STORE_TILE

    // ---- epilogue ----
    const int gn0 = blockIdx.x*128 + tx*4;
    float badd[8];
    if (EPI == 0) {
        #pragma unroll
        for (int j = 0; j < 4; j++) {
            badd[j]   = bias ? bias[gn0 + j]      : 0.f;
            badd[4+j] = bias ? bias[gn0 + 64 + j] : 0.f;
        }
    } else {
        const float* sqc = sqv + (size_t)bz*sqStride;
        #pragma unroll
        for (int j = 0; j < 4; j++) { badd[j] = sqc[gn0 + j]; badd[4+j] = sqc[gn0 + 64 + j]; }
    }

    float* Cb = C + (size_t)bz*bsC;
    #pragma unroll
    for (int i = 0; i < 8; i++) {
        const int gm = blockIdx.y*128 + ty*4 + (i & 3) + ((i >> 2) << 6);
        float cc[8];
        #pragma unroll
        for (int jj = 0; jj < 4; jj++) { float lo, hi; unpack2(acc2[i][jj], lo, hi); cc[2*jj] = lo; cc[2*jj+1] = hi; }
        float4 o0, o1;
        if (EPI == 0) {
            o0 = make_float4(cc[0]+badd[0], cc[1]+badd[1], cc[2]+badd[2], cc[3]+badd[3]);
            o1 = make_float4(cc[4]+badd[4], cc[5]+badd[5], cc[6]+badd[6], cc[7]+badd[7]);
        } else {
            const float rs = sqv[(size_t)bz*sqStride + gm];
            o0 = make_float4(rs+badd[0]-2.f*cc[0], rs+badd[1]-2.f*cc[1],
                             rs+badd[2]-2.f*cc[2], rs+badd[3]-2.f*cc[3]);
            o1 = make_float4(rs+badd[4]-2.f*cc[4], rs+badd[5]-2.f*cc[5],
                             rs+badd[6]-2.f*cc[6], rs+badd[7]-2.f*cc[7]);
        }
        *(float4*)&Cb[(size_t)gm*ldc + gn0]      = o0;
        *(float4*)&Cb[(size_t)gm*ldc + gn0 + 64] = o1;
    }
}

// ---------------------------------------------------------------------------
// GEMM wrappers (bind device-global scratch — keeps kernel_launch launch-only)
// ---------------------------------------------------------------------------
__global__ void __launch_bounds__(256, 2) gemm_p(const float* x, const float* w1w) {
    sgemm_body<0,0>(x, CIN, 0, w1w, CIN, 0, 0, -1, nullptr,
                    g_p, CIN, 0, CIN, nullptr, 0, nullptr, nullptr, nullptr);
}
__global__ void __launch_bounds__(256, 2) gemm_v(const float* x, const float* x1w) {
    sgemm_body<0,0>(x, CIN, 0, x1w, 256, 0, 128, -1, nullptr,
                    g_v, FO, 0, CIN, nullptr, 0, nullptr, nullptr, nullptr);
}
__global__ void __launch_bounds__(256, 2) gemm_u(const float* x, const float* x1w, const float* x1b) {
    sgemm_body<0,0>(x, CIN, 0, x1w, 256, 0, 0, 128, x1b,
                    g_u, FO, 0, CIN, nullptr, 0, nullptr, nullptr, nullptr);
}
__global__ void __launch_bounds__(256, 2) gemm_dist(const float* x) {
    sgemm_body<0,1>(x, CIN, (size_t)NP*CIN, x, CIN, (size_t)NP*CIN, 0, -1, nullptr,
                    g_dist, NP, (size_t)NP*NP, CIN, g_sq, NP, nullptr, nullptr, nullptr);
}
// Fused: A = lrelu(p[nbr]-p[pt]+w1b) built on the fly
__global__ void __launch_bounds__(256, 2) gemm_S(const float* w2w, const float* w2b,
                                                 const float* w1b) {
    sgemm_body<2,0>(nullptr, 0, 0, w2w, CIN, 0, 0, -1, w2b,
                    g_S, FO, 0, CIN, nullptr, 0, g_p, nullptr, w1b);
}
// Fused: A = lrelu(u[pt]+v[nbr]) built on the fly
__global__ void __launch_bounds__(256, 2) gemm_H(const float* x2w, const float* x2b) {
    sgemm_body<3,0>(nullptr, 0, 0, x2w, FO, 0, 0, -1, x2b,
                    g_H, FO, 0, FO, nullptr, 0, g_u, g_v, nullptr);
}

// ---------------------------------------------------------------------------
// ||x||^2 per point: one warp per row of 128 floats
// ---------------------------------------------------------------------------
__global__ void __launch_bounds__(256) sq_kernel(const float* __restrict__ x) {
    const int row  = blockIdx.x*8 + (threadIdx.x >> 5);
    const int lane = threadIdx.x & 31;
    float4 v = ((const float4*)(x + (size_t)row*CIN))[lane];
    float s = v.x*v.x + v.y*v.y + v.z*v.z + v.w*v.w;
    #pragma unroll
    for (int off = 16; off > 0; off >>= 1) s += __shfl_xor_sync(0xffffffffu, s, off);
    if (lane == 0) g_sq[row] = s;
}

// ---------------------------------------------------------------------------
// Top-20 nearest (excluding self): one warp per query row.
// ---------------------------------------------------------------------------
__global__ void __launch_bounds__(256) topk_kernel() {
    const int gw   = blockIdx.x*8 + (threadIdx.x >> 5);
    const int lane = threadIdx.x & 31;
    const int n    = gw & (NP - 1);
    const float* row = g_dist + (size_t)gw * NP;

    ull best[KNN];
    #pragma unroll
    for (int j = 0; j < KNN; j++) best[j] = ~0ull;
    ull curmax = ~0ull; int maxslot = 0;

    for (int m = lane; m < NP; m += 32) {
        if (m == n) continue;
        float d = row[m];
        unsigned ub = __float_as_uint(d);
        ub = (ub & 0x80000000u) ? ~ub : (ub | 0x80000000u);
        ull key = ((ull)ub << 32) | (unsigned)m;
        if (key < curmax) {
            #pragma unroll
            for (int j = 0; j < KNN; j++) if (j == maxslot) best[j] = key;
            curmax = best[0]; maxslot = 0;
            #pragma unroll
            for (int j = 1; j < KNN; j++) if (best[j] > curmax) { curmax = best[j]; maxslot = j; }
        }
    }

    #pragma unroll 1
    for (int r = 0; r < KNN; r++) {
        ull lmin = best[0]; int ls = 0;
        #pragma unroll
        for (int j = 1; j < KNN; j++) if (best[j] < lmin) { lmin = best[j]; ls = j; }
        ull wmin = lmin;
        #pragma unroll
        for (int off = 16; off > 0; off >>= 1) {
            ull o = __shfl_xor_sync(0xffffffffu, wmin, off);
            if (o < wmin) wmin = o;
        }
        if (lmin == wmin) {
            #pragma unroll
            for (int j = 0; j < KNN; j++) if (j == ls) best[j] = ~0ull;
        }
        if (lane == 0) g_idx[gw*KNN + r] = (int)(wmin & 0xffffffffull);
    }
}

// ---------------------------------------------------------------------------
// Softmax over K + weighted sum:  out[bn,c] = sum_k H*softmax_k(S)
// ---------------------------------------------------------------------------
__global__ void __launch_bounds__(256) smax_kernel(float* __restrict__ out) {
    const int bn = blockIdx.x;
    const int c  = threadIdx.x;
    const size_t base = (size_t)bn*KNN*FO + c;

    float sv[KNN];
    float mx = -3.4e38f;
    #pragma unroll
    for (int k = 0; k < KNN; k++) { sv[k] = g_S[base + (size_t)k*FO]; mx = fmaxf(mx, sv[k]); }
    float sum = 0.f, acc = 0.f;
    #pragma unroll
    for (int k = 0; k < KNN; k++) {
        float e = expf(sv[k] - mx);
        sum += e;
        acc += e * g_H[base + (size_t)k*FO];
    }
    out[(size_t)bn*FO + c] = acc / sum;
}

// ---------------------------------------------------------------------------
// Launch
// ---------------------------------------------------------------------------
extern "C" void kernel_launch(void* const* d_in, const int* in_sizes, int n_in,
                              void* d_out, int out_size) {
    const float* x   = (const float*)d_in[0];
    const float* w1w = (const float*)d_in[1];
    const float* w1b = (const float*)d_in[2];
    const float* w2w = (const float*)d_in[3];
    const float* w2b = (const float*)d_in[4];
    const float* x1w = (const float*)d_in[5];
    const float* x1b = (const float*)d_in[6];
    const float* x2w = (const float*)d_in[7];
    const float* x2b = (const float*)d_in[8];
    float* out = (float*)d_out;

    // Per-point squared norms + per-point linear features
    sq_kernel<<<BNP/8, 256>>>(x);
    gemm_p<<<dim3(1, BNP/128, 1), 256>>>(x, w1w);
    gemm_v<<<dim3(2, BNP/128, 1), 256>>>(x, x1w);
    gemm_u<<<dim3(2, BNP/128, 1), 256>>>(x, x1w, x1b);

    // Pairwise distances (per batch) + top-20 neighbors
    gemm_dist<<<dim3(NP/128, NP/128, NB), 256>>>(x);
    topk_kernel<<<BNP/8, 256>>>();

    // Per-edge GEMMs with fused gather+lrelu A-loaders
    gemm_S<<<dim3(2, NE/128, 1), 256>>>(w2w, w2b, w1b);
    gemm_H<<<dim3(2, NE/128, 1), 256>>>(x2w, x2b);

    // Softmax over K + weighted reduction -> output (B,N,256)
    smax_kernel<<<BNP, 256>>>(out);
}

// round 15
// speedup vs baseline: 1.6063x; 1.0008x over previous
#include <cuda_runtime.h>

// Problem constants
#define NB   4
#define NP   4096
#define CIN  128
#define FO   256
#define KNN  20
#define BNP  (NB*NP)          // 16384 points
#define NE   (BNP*KNN)        // 327680 edges

// ---------------------------------------------------------------------------
// Scratch (device globals — allocation-free kernel_launch)
// ---------------------------------------------------------------------------
__device__ float g_p   [(size_t)BNP*CIN];        // w1_w @ x        (per point)
__device__ float g_u   [(size_t)BNP*FO];         // (A1-B1)@x + b1  (per point)
__device__ float g_v   [(size_t)BNP*FO];         // B1@x            (per point)
__device__ float g_sq  [BNP];                    // ||x||^2 per point
__device__ float g_dist[(size_t)NB*NP*NP];       // pairwise distances
__device__ int   g_idx [NE];                     // knn indices (within batch)
__device__ float g_S   [(size_t)NE*FO];          // w2 output per edge
__device__ float g_H   [(size_t)NE*FO];          // x2 output per edge

typedef unsigned long long ull;

// ---------------------------------------------------------------------------
// f32x2 packed-FMA helpers (Blackwell FFMA2 path)
// ---------------------------------------------------------------------------
__device__ __forceinline__ ull bcast2(float x) {
    ull r; asm("mov.b64 %0, {%1, %1};" : "=l"(r) : "f"(x)); return r;
}
__device__ __forceinline__ void fma2(ull &d, ull a, ull b) {
    asm("fma.rn.f32x2 %0, %1, %2, %0;" : "+l"(d) : "l"(a), "l"(b));
}
__device__ __forceinline__ void unpack2(ull v, float &lo, float &hi) {
    asm("mov.b64 {%0, %1}, %2;" : "=f"(lo), "=f"(hi) : "l"(v));
}
__device__ __forceinline__ float lrelu_f(float x) { return fmaxf(x, 0.2f*x); }

// ---------------------------------------------------------------------------
// SGEMM v2:  C[m][n] = sum_k Aeff[m][k] * Weff[n][k]  (+ epilogue)
//
//  AMODE 0: Aeff = A[m*lda + k]                       (plain)
//  AMODE 2: Aeff = lrelu(p[nbr(m)][k] - p[pt(m)][k] + w1b[k])   (fused Q)
//  AMODE 3: Aeff = lrelu(u[pt(m)][k] + v[nbr(m)][k])            (fused R)
//  Weff[n][k] = W[n*ldw + wOff + k] (- W[n*ldw + wSub + k] if wSub>=0)
//
//  EPI 0: C = acc + bias[n] (bias may be null)
//  EPI 1: C = sq[m] + sq[n] - 2*acc  (distance, batched by blockIdx.z)
//
// BM=BN=128, BK=8, 256 threads, 8x8 micro-tile, f32x2 accumulators.
// Double-buffered smem (1 sync/tile) + register-double-buffered fragments.
// ---------------------------------------------------------------------------
template<int AMODE, int EPI>
__device__ __forceinline__ void sgemm_body(
    const float* __restrict__ A, int lda, size_t bsA,
    const float* __restrict__ W, int ldw, size_t bsW, int wOff, int wSub,
    const float* __restrict__ bias,
    float* __restrict__ C, int ldc, size_t bsC,
    int Kd, const float* __restrict__ sqv, int sqStride,
    const float* __restrict__ P0, const float* __restrict__ P1,
    const float* __restrict__ w1b)
{
    __shared__ __align__(16) float As[2][8][128];
    __shared__ __align__(16) float Bs[2][8][128];

    const int tid  = threadIdx.x;
    const int lrow = tid & 127;          // row within tile (load mapping)
    const int lk   = (tid >> 7) * 4;     // k-quad within BK=8
    const int tx   = tid & 15;
    const int ty   = tid >> 4;
    const int bz   = blockIdx.z;

    const int am = blockIdx.y*128 + lrow;     // global A row (point or edge)

    // Fused-loader precompute (edge -> (point, neighbor) indices)
    int ebn = 0, enbr = 0;
    if (AMODE >= 2) {
        ebn  = am / KNN;
        enbr = ((ebn >> 12) << 12) + g_idx[am];
    }

    const float* Abase = (AMODE == 0)
        ? (A + (size_t)bz*bsA + (size_t)am*lda + lk) : nullptr;
    const float* Wbase = W + (size_t)bz*bsW
        + (size_t)(blockIdx.x*128 + lrow)*ldw + lk;

    ull acc2[8][4];
    #pragma unroll
    for (int i = 0; i < 8; i++)
        #pragma unroll
        for (int j = 0; j < 4; j++) acc2[i][j] = 0ull;

    const int nK = Kd >> 3;

    // ---- operand loaders (4 floats per thread per tile per operand) ----
    #define LOAD_A(kbase, out) do {                                          \
        if (AMODE == 0) {                                                     \
            float4 t = *(const float4*)(Abase + (kbase));                     \
            out[0]=t.x; out[1]=t.y; out[2]=t.z; out[3]=t.w;                   \
        } else if (AMODE == 2) {                                              \
            float4 a = *(const float4*)(P0 + (size_t)enbr*CIN + (kbase) + lk);\
            float4 b = *(const float4*)(P0 + (size_t)ebn *CIN + (kbase) + lk);\
            float4 w = *(const float4*)(w1b + (kbase) + lk);                  \
            out[0]=lrelu_f(a.x-b.x+w.x); out[1]=lrelu_f(a.y-b.y+w.y);         \
            out[2]=lrelu_f(a.z-b.z+w.z); out[3]=lrelu_f(a.w-b.w+w.w);         \
        } else {                                                              \
            float4 a = *(const float4*)(P0 + (size_t)ebn *FO + (kbase) + lk); \
            float4 b = *(const float4*)(P1 + (size_t)enbr*FO + (kbase) + lk); \
            out[0]=lrelu_f(a.x+b.x); out[1]=lrelu_f(a.y+b.y);                 \
            out[2]=lrelu_f(a.z+b.z); out[3]=lrelu_f(a.w+b.w);                 \
        }                                                                     \
    } while (0)

    #define LOAD_W(kbase, out) do {                                          \
        float4 t = *(const float4*)(Wbase + wOff + (kbase));                  \
        if (wSub >= 0) {                                                      \
            float4 s = *(const float4*)(Wbase + wSub + (kbase));              \
            t.x-=s.x; t.y-=s.y; t.z-=s.z; t.w-=s.w;                           \
        }                                                                     \
        out[0]=t.x; out[1]=t.y; out[2]=t.z; out[3]=t.w;                       \
    } while (0)

    #define STORE_TILE(buf, ra, rw) do {                                     \
        _Pragma("unroll")                                                     \
        for (int j = 0; j < 4; j++) {                                         \
            As[buf][lk+j][lrow] = ra[j];                                      \
            Bs[buf][lk+j][lrow] = rw[j];                                      \
        }                                                                     \
    } while (0)

    // prologue: tile 0 -> smem[0]
    {
        float ra[4], rw[4];
        LOAD_A(0, ra); LOAD_W(0, rw);
        STORE_TILE(0, ra, rw);
    }
    __syncthreads();

    int buf = 0;
    for (int kt = 0; kt < nK; kt++) {
        float na[4], nw[4];
        const bool more = (kt + 1 < nK);
        if (more) { LOAD_A((kt+1)*8, na); LOAD_W((kt+1)*8, nw); }

        // 8 k-steps, register double-buffered fragments
        float af[2][8];
        ull   bf[2][4];
        {
            float4 a0 = *(const float4*)&As[buf][0][ty*4];
            float4 a1 = *(const float4*)&As[buf][0][ty*4 + 64];
            af[0][0]=a0.x; af[0][1]=a0.y; af[0][2]=a0.z; af[0][3]=a0.w;
            af[0][4]=a1.x; af[0][5]=a1.y; af[0][6]=a1.z; af[0][7]=a1.w;
            ulonglong2 b0 = *(const ulonglong2*)&Bs[buf][0][tx*4];
            ulonglong2 b1 = *(const ulonglong2*)&Bs[buf][0][tx*4 + 64];
            bf[0][0]=b0.x; bf[0][1]=b0.y; bf[0][2]=b1.x; bf[0][3]=b1.y;
        }
        #pragma unroll
        for (int k = 0; k < 8; k++) {
            const int cur = k & 1, nxt = cur ^ 1;
            if (k < 7) {
                float4 a0 = *(const float4*)&As[buf][k+1][ty*4];
                float4 a1 = *(const float4*)&As[buf][k+1][ty*4 + 64];
                af[nxt][0]=a0.x; af[nxt][1]=a0.y; af[nxt][2]=a0.z; af[nxt][3]=a0.w;
                af[nxt][4]=a1.x; af[nxt][5]=a1.y; af[nxt][6]=a1.z; af[nxt][7]=a1.w;
                ulonglong2 b0 = *(const ulonglong2*)&Bs[buf][k+1][tx*4];
                ulonglong2 b1 = *(const ulonglong2*)&Bs[buf][k+1][tx*4 + 64];
                bf[nxt][0]=b0.x; bf[nxt][1]=b0.y; bf[nxt][2]=b1.x; bf[nxt][3]=b1.y;
            }
            #pragma unroll
            for (int i = 0; i < 8; i++) {
                ull ai = bcast2(af[cur][i]);
                #pragma unroll
                for (int jj = 0; jj < 4; jj++) fma2(acc2[i][jj], ai, bf[cur][jj]);
            }
        }

        if (more) STORE_TILE(buf ^ 1, na, nw);
        __syncthreads();
        buf ^= 1;
    }

    #undef LOAD_A
    #undef LOAD_W
    #undef STORE_TILE

    // ---- epilogue ----
    const int gn0 = blockIdx.x*128 + tx*4;
    float badd[8];
    if (EPI == 0) {
        #pragma unroll
        for (int j = 0; j < 4; j++) {
            badd[j]   = bias ? bias[gn0 + j]      : 0.f;
            badd[4+j] = bias ? bias[gn0 + 64 + j] : 0.f;
        }
    } else {
        const float* sqc = sqv + (size_t)bz*sqStride;
        #pragma unroll
        for (int j = 0; j < 4; j++) { badd[j] = sqc[gn0 + j]; badd[4+j] = sqc[gn0 + 64 + j]; }
    }

    float* Cb = C + (size_t)bz*bsC;
    #pragma unroll
    for (int i = 0; i < 8; i++) {
        const int gm = blockIdx.y*128 + ty*4 + (i & 3) + ((i >> 2) << 6);
        float cc[8];
        #pragma unroll
        for (int jj = 0; jj < 4; jj++) { float lo, hi; unpack2(acc2[i][jj], lo, hi); cc[2*jj] = lo; cc[2*jj+1] = hi; }
        float4 o0, o1;
        if (EPI == 0) {
            o0 = make_float4(cc[0]+badd[0], cc[1]+badd[1], cc[2]+badd[2], cc[3]+badd[3]);
            o1 = make_float4(cc[4]+badd[4], cc[5]+badd[5], cc[6]+badd[6], cc[7]+badd[7]);
        } else {
            const float rs = sqv[(size_t)bz*sqStride + gm];
            o0 = make_float4(rs+badd[0]-2.f*cc[0], rs+badd[1]-2.f*cc[1],
                             rs+badd[2]-2.f*cc[2], rs+badd[3]-2.f*cc[3]);
            o1 = make_float4(rs+badd[4]-2.f*cc[4], rs+badd[5]-2.f*cc[5],
                             rs+badd[6]-2.f*cc[6], rs+badd[7]-2.f*cc[7]);
        }
        *(float4*)&Cb[(size_t)gm*ldc + gn0]      = o0;
        *(float4*)&Cb[(size_t)gm*ldc + gn0 + 64] = o1;
    }
}

// ---------------------------------------------------------------------------
// GEMM wrappers (bind device-global scratch — keeps kernel_launch launch-only)
// ---------------------------------------------------------------------------
__global__ void __launch_bounds__(256, 2) gemm_p(const float* x, const float* w1w) {
    sgemm_body<0,0>(x, CIN, 0, w1w, CIN, 0, 0, -1, nullptr,
                    g_p, CIN, 0, CIN, nullptr, 0, nullptr, nullptr, nullptr);
}
__global__ void __launch_bounds__(256, 2) gemm_v(const float* x, const float* x1w) {
    sgemm_body<0,0>(x, CIN, 0, x1w, 256, 0, 128, -1, nullptr,
                    g_v, FO, 0, CIN, nullptr, 0, nullptr, nullptr, nullptr);
}
__global__ void __launch_bounds__(256, 2) gemm_u(const float* x, const float* x1w, const float* x1b) {
    sgemm_body<0,0>(x, CIN, 0, x1w, 256, 0, 0, 128, x1b,
                    g_u, FO, 0, CIN, nullptr, 0, nullptr, nullptr, nullptr);
}
__global__ void __launch_bounds__(256, 2) gemm_dist(const float* x) {
    sgemm_body<0,1>(x, CIN, (size_t)NP*CIN, x, CIN, (size_t)NP*CIN, 0, -1, nullptr,
                    g_dist, NP, (size_t)NP*NP, CIN, g_sq, NP, nullptr, nullptr, nullptr);
}
// Fused: A = lrelu(p[nbr]-p[pt]+w1b) built on the fly
__global__ void __launch_bounds__(256, 2) gemm_S(const float* w2w, const float* w2b,
                                                 const float* w1b) {
    sgemm_body<2,0>(nullptr, 0, 0, w2w, CIN, 0, 0, -1, w2b,
                    g_S, FO, 0, CIN, nullptr, 0, g_p, nullptr, w1b);
}
// Fused: A = lrelu(u[pt]+v[nbr]) built on the fly
__global__ void __launch_bounds__(256, 2) gemm_H(const float* x2w, const float* x2b) {
    sgemm_body<3,0>(nullptr, 0, 0, x2w, FO, 0, 0, -1, x2b,
                    g_H, FO, 0, FO, nullptr, 0, g_u, g_v, nullptr);
}

// ---------------------------------------------------------------------------
// ||x||^2 per point: one warp per row of 128 floats
// ---------------------------------------------------------------------------
__global__ void __launch_bounds__(256) sq_kernel(const float* __restrict__ x) {
    const int row  = blockIdx.x*8 + (threadIdx.x >> 5);
    const int lane = threadIdx.x & 31;
    float4 v = ((const float4*)(x + (size_t)row*CIN))[lane];
    float s = v.x*v.x + v.y*v.y + v.z*v.z + v.w*v.w;
    #pragma unroll
    for (int off = 16; off > 0; off >>= 1) s += __shfl_xor_sync(0xffffffffu, s, off);
    if (lane == 0) g_sq[row] = s;
}

// ---------------------------------------------------------------------------
// Top-20 nearest (excluding self): one warp per query row.
// ---------------------------------------------------------------------------
__global__ void __launch_bounds__(256) topk_kernel() {
    const int gw   = blockIdx.x*8 + (threadIdx.x >> 5);
    const int lane = threadIdx.x & 31;
    const int n    = gw & (NP - 1);
    const float* row = g_dist + (size_t)gw * NP;

    ull best[KNN];
    #pragma unroll
    for (int j = 0; j < KNN; j++) best[j] = ~0ull;
    ull curmax = ~0ull; int maxslot = 0;

    for (int m = lane; m < NP; m += 32) {
        if (m == n) continue;
        float d = row[m];
        unsigned ub = __float_as_uint(d);
        ub = (ub & 0x80000000u) ? ~ub : (ub | 0x80000000u);
        ull key = ((ull)ub << 32) | (unsigned)m;
        if (key < curmax) {
            #pragma unroll
            for (int j = 0; j < KNN; j++) if (j == maxslot) best[j] = key;
            curmax = best[0]; maxslot = 0;
            #pragma unroll
            for (int j = 1; j < KNN; j++) if (best[j] > curmax) { curmax = best[j]; maxslot = j; }
        }
    }

    #pragma unroll 1
    for (int r = 0; r < KNN; r++) {
        ull lmin = best[0]; int ls = 0;
        #pragma unroll
        for (int j = 1; j < KNN; j++) if (best[j] < lmin) { lmin = best[j]; ls = j; }
        ull wmin = lmin;
        #pragma unroll
        for (int off = 16; off > 0; off >>= 1) {
            ull o = __shfl_xor_sync(0xffffffffu, wmin, off);
            if (o < wmin) wmin = o;
        }
        if (lmin == wmin) {
            #pragma unroll
            for (int j = 0; j < KNN; j++) if (j == ls) best[j] = ~0ull;
        }
        if (lane == 0) g_idx[gw*KNN + r] = (int)(wmin & 0xffffffffull);
    }
}

// ---------------------------------------------------------------------------
// Softmax over K + weighted sum:  out[bn,c] = sum_k H*softmax_k(S)
// ---------------------------------------------------------------------------
__global__ void __launch_bounds__(256) smax_kernel(float* __restrict__ out) {
    const int bn = blockIdx.x;
    const int c  = threadIdx.x;
    const size_t base = (size_t)bn*KNN*FO + c;

    float sv[KNN];
    float mx = -3.4e38f;
    #pragma unroll
    for (int k = 0; k < KNN; k++) { sv[k] = g_S[base + (size_t)k*FO]; mx = fmaxf(mx, sv[k]); }
    float sum = 0.f, acc = 0.f;
    #pragma unroll
    for (int k = 0; k < KNN; k++) {
        float e = expf(sv[k] - mx);
        sum += e;
        acc += e * g_H[base + (size_t)k*FO];
    }
    out[(size_t)bn*FO + c] = acc / sum;
}

// ---------------------------------------------------------------------------
// Launch
// ---------------------------------------------------------------------------
extern "C" void kernel_launch(void* const* d_in, const int* in_sizes, int n_in,
                              void* d_out, int out_size) {
    const float* x   = (const float*)d_in[0];
    const float* w1w = (const float*)d_in[1];
    const float* w1b = (const float*)d_in[2];
    const float* w2w = (const float*)d_in[3];
    const float* w2b = (const float*)d_in[4];
    const float* x1w = (const float*)d_in[5];
    const float* x1b = (const float*)d_in[6];
    const float* x2w = (const float*)d_in[7];
    const float* x2b = (const float*)d_in[8];
    float* out = (float*)d_out;

    // Per-point squared norms + per-point linear features
    sq_kernel<<<BNP/8, 256>>>(x);
    gemm_p<<<dim3(1, BNP/128, 1), 256>>>(x, w1w);
    gemm_v<<<dim3(2, BNP/128, 1), 256>>>(x, x1w);
    gemm_u<<<dim3(2, BNP/128, 1), 256>>>(x, x1w, x1b);

    // Pairwise distances (per batch) + top-20 neighbors
    gemm_dist<<<dim3(NP/128, NP/128, NB), 256>>>(x);
    topk_kernel<<<BNP/8, 256>>>();

    // Per-edge GEMMs with fused gather+lrelu A-loaders
    gemm_S<<<dim3(2, NE/128, 1), 256>>>(w2w, w2b, w1b);
    gemm_H<<<dim3(2, NE/128, 1), 256>>>(x2w, x2b);

    // Softmax over K + weighted reduction -> output (B,N,256)
    smax_kernel<<<BNP, 256>>>(out);
}